// round 1
// baseline (speedup 1.0000x reference)
#include <cuda_runtime.h>
#include <cuda_bf16.h>

// Problem constants
#define BB 32      // batch
#define TT 200     // timesteps
#define EE 32      // input dim
#define HH 128     // hidden dim
#define VV 8000    // vocab
#define MM (BB*TT) // 6400 GEMM rows

// Scratch (static device allocations are allowed; runtime allocs are not)
__device__ float g_ux[BB * TT * HH];   // [b][t][h]
__device__ float g_hs[BB * TT * HH];   // [b][t][h]

// ---------------------------------------------------------------------------
// Kernel A: ux[b][t][h] = Uw[h,:]·x[b,t,:] + Ub[h] + Wb[h]
// grid = B*T blocks, 128 threads
// ---------------------------------------------------------------------------
__global__ __launch_bounds__(HH) void ux_kernel(const float* __restrict__ x,
                                                const float* __restrict__ Uw,
                                                const float* __restrict__ Ub,
                                                const float* __restrict__ Wb) {
    int bt = blockIdx.x;        // = b*TT + t  (x and g_ux share this layout)
    int j  = threadIdx.x;
    __shared__ float xs[EE];
    if (j < EE) xs[j] = x[bt * EE + j];
    __syncthreads();
    float acc = Ub[j] + Wb[j];
    const float* uwr = Uw + j * EE;
#pragma unroll
    for (int e = 0; e < EE; e++) acc += uwr[e] * xs[e];
    g_ux[bt * HH + j] = acc;
}

// ---------------------------------------------------------------------------
// Kernel B: per-batch independent recurrence. 32 CTAs, 128 threads.
// Thread j holds Ww row j in registers; h broadcast via shared (double buffer).
// ---------------------------------------------------------------------------
__global__ __launch_bounds__(HH, 1) void recurrence_kernel(const float* __restrict__ Ww,
                                                           float* __restrict__ hidden_out) {
    int b = blockIdx.x;
    int j = threadIdx.x;

    __shared__ float4 hbuf[2][HH / 4];  // h as 32 float4, double buffered

    // Ww row j -> registers (fully unrolled so all 128 stay in regs)
    float w[HH];
    const float4* wrow = (const float4*)(Ww + j * HH);
#pragma unroll
    for (int k = 0; k < HH / 4; k++) {
        float4 v = wrow[k];
        w[4 * k + 0] = v.x; w[4 * k + 1] = v.y;
        w[4 * k + 2] = v.z; w[4 * k + 3] = v.w;
    }

    if (j < HH / 4) hbuf[0][j] = make_float4(0.f, 0.f, 0.f, 0.f);
    __syncthreads();

    const float* uxb = g_ux + b * TT * HH;
    float*       hsb = g_hs + b * TT * HH;

    int cur = 0;
    float hv = 0.f;
    float ux_next = uxb[j];  // prefetch t=0
    for (int t = 0; t < TT; t++) {
        float uxv = ux_next;
        if (t + 1 < TT) ux_next = uxb[(t + 1) * HH + j];

        float acc0 = 0.f, acc1 = 0.f, acc2 = 0.f, acc3 = 0.f;
#pragma unroll
        for (int k = 0; k < HH / 4; k++) {
            float4 h4 = hbuf[cur][k];
            acc0 += w[4 * k + 0] * h4.x;
            acc1 += w[4 * k + 1] * h4.y;
            acc2 += w[4 * k + 2] * h4.z;
            acc3 += w[4 * k + 3] * h4.w;
        }
        hv = tanhf(uxv + (acc0 + acc1) + (acc2 + acc3));

        int nxt = cur ^ 1;
        ((float*)hbuf[nxt])[j] = hv;
        hsb[t * HH + j] = hv;
        __syncthreads();   // publishes nxt AND guarantees all reads of cur done
        cur = nxt;
    }
    hidden_out[b * HH + j] = hv;
}

// ---------------------------------------------------------------------------
// Kernel C: out[m][n] = sum_k hs[m][k] * Vw[n][k] + Vb[n]
// Classic fp32 SIMT GEMM. BM=BN=128, BK=16, 256 threads, 8x8 microtiles.
// M = 6400 (multiple of 128), N = 8000 (guarded).
// ---------------------------------------------------------------------------
#define BM 128
#define BN 128
#define BK 16

__global__ __launch_bounds__(256) void gemm_kernel(const float* __restrict__ Bmat,  // Vw [N][K]
                                                   const float* __restrict__ bias,  // Vb [N]
                                                   float* __restrict__ C) {
    __shared__ float As[BK][BM];
    __shared__ float Bs[BK][BN];

    const int K = HH;
    const int N = VV;
    int mtile = blockIdx.y * BM;
    int ntile = blockIdx.x * BN;
    int tid = threadIdx.x;
    int ty = tid >> 4;       // 0..15 (m dir)
    int tx = tid & 15;       // 0..15 (n dir)

    float acc[8][8];
#pragma unroll
    for (int i = 0; i < 8; i++)
#pragma unroll
        for (int jj = 0; jj < 8; jj++) acc[i][jj] = 0.f;

    const float* A = g_hs;
    int lrow = tid >> 1;          // 0..127
    int lc4  = (tid & 1) * 2;     // 0 or 2 (float4 index along K)

    for (int k0 = 0; k0 < K; k0 += BK) {
        // load A tile (transposed into As[k][m])
        {
            const float4* src = (const float4*)(A + (size_t)(mtile + lrow) * K + k0);
            float4 v0 = src[lc4];
            float4 v1 = src[lc4 + 1];
            int kb = lc4 * 4;
            As[kb + 0][lrow] = v0.x; As[kb + 1][lrow] = v0.y;
            As[kb + 2][lrow] = v0.z; As[kb + 3][lrow] = v0.w;
            As[kb + 4][lrow] = v1.x; As[kb + 5][lrow] = v1.y;
            As[kb + 6][lrow] = v1.z; As[kb + 7][lrow] = v1.w;
        }
        // load B tile (Vw rows) with N guard
        {
            int n = ntile + lrow;
            float4 v0 = make_float4(0.f, 0.f, 0.f, 0.f);
            float4 v1 = v0;
            if (n < N) {
                const float4* src = (const float4*)(Bmat + (size_t)n * K + k0);
                v0 = src[lc4];
                v1 = src[lc4 + 1];
            }
            int kb = lc4 * 4;
            Bs[kb + 0][lrow] = v0.x; Bs[kb + 1][lrow] = v0.y;
            Bs[kb + 2][lrow] = v0.z; Bs[kb + 3][lrow] = v0.w;
            Bs[kb + 4][lrow] = v1.x; Bs[kb + 5][lrow] = v1.y;
            Bs[kb + 6][lrow] = v1.z; Bs[kb + 7][lrow] = v1.w;
        }
        __syncthreads();

#pragma unroll
        for (int k = 0; k < BK; k++) {
            float4 a0 = *(const float4*)&As[k][ty * 8];
            float4 a1 = *(const float4*)&As[k][ty * 8 + 4];
            float4 b0 = *(const float4*)&Bs[k][tx * 8];
            float4 b1 = *(const float4*)&Bs[k][tx * 8 + 4];
            float ar[8] = {a0.x, a0.y, a0.z, a0.w, a1.x, a1.y, a1.z, a1.w};
            float br[8] = {b0.x, b0.y, b0.z, b0.w, b1.x, b1.y, b1.z, b1.w};
#pragma unroll
            for (int i = 0; i < 8; i++)
#pragma unroll
                for (int jj = 0; jj < 8; jj++)
                    acc[i][jj] += ar[i] * br[jj];
        }
        __syncthreads();
    }

    // epilogue: + bias, store. m rows always valid; n guarded on last tile.
    bool full = (ntile + BN) <= N;
#pragma unroll
    for (int i = 0; i < 8; i++) {
        int m = mtile + ty * 8 + i;
        float* crow = C + (size_t)m * N;
        if (full) {
#pragma unroll
            for (int q = 0; q < 2; q++) {
                int n = ntile + tx * 8 + q * 4;
                float4 r;
                r.x = acc[i][q * 4 + 0] + bias[n + 0];
                r.y = acc[i][q * 4 + 1] + bias[n + 1];
                r.z = acc[i][q * 4 + 2] + bias[n + 2];
                r.w = acc[i][q * 4 + 3] + bias[n + 3];
                *(float4*)(crow + n) = r;
            }
        } else {
#pragma unroll
            for (int jj = 0; jj < 8; jj++) {
                int n = ntile + tx * 8 + jj;
                if (n < N) crow[n] = acc[i][jj] + bias[n];
            }
        }
    }
}

// ---------------------------------------------------------------------------
extern "C" void kernel_launch(void* const* d_in, const int* in_sizes, int n_in,
                              void* d_out, int out_size) {
    const float* x  = (const float*)d_in[0];
    const float* Ww = (const float*)d_in[1];
    const float* Wb = (const float*)d_in[2];
    const float* Uw = (const float*)d_in[3];
    const float* Ub = (const float*)d_in[4];
    const float* Vw = (const float*)d_in[5];
    const float* Vb = (const float*)d_in[6];

    float* out    = (float*)d_out;                       // [B][T][V]
    float* hidden = out + (size_t)BB * TT * VV;          // [B][H]

    ux_kernel<<<BB * TT, HH>>>(x, Uw, Ub, Wb);
    recurrence_kernel<<<BB, HH>>>(Ww, hidden);
    dim3 grid((VV + BN - 1) / BN, MM / BM);
    gemm_kernel<<<grid, 256>>>(Vw, Vb, out);
}

// round 3
// speedup vs baseline: 2.2329x; 2.2329x over previous
#include <cuda_runtime.h>
#include <cuda_bf16.h>
#include <cstdint>

// Problem constants
#define BB 32
#define TT 200
#define EE 32
#define HH 128
#define VV 8000
#define MM (BB*TT)   // 6400

// Static scratch: bf16 hi/lo splits
__device__ alignas(256) __nv_bfloat16 g_hs_hi[MM * HH];
__device__ alignas(256) __nv_bfloat16 g_hs_lo[MM * HH];
__device__ alignas(256) __nv_bfloat16 g_vw_hi[VV * HH];
__device__ alignas(256) __nv_bfloat16 g_vw_lo[VV * HH];

// ---------------------------------------------------------------------------
// helpers (portable PTX only: ldmatrix / mma.sync / cp.async — no tcgen05)
// ---------------------------------------------------------------------------
__device__ __forceinline__ uint32_t smem_u32(const void* p) {
    uint32_t a;
    asm("{ .reg .u64 t; cvta.to.shared.u64 t, %1; cvt.u32.u64 %0, t; }"
        : "=r"(a) : "l"(p));
    return a;
}
__device__ __forceinline__ void cpasync16(uint32_t dst, const void* src) {
    asm volatile("cp.async.cg.shared.global [%0], [%1], 16;" :: "r"(dst), "l"(src));
}
__device__ __forceinline__ void cpasync_commit_wait() {
    asm volatile("cp.async.commit_group;" ::: "memory");
    asm volatile("cp.async.wait_group 0;" ::: "memory");
}
__device__ __forceinline__ void ldsm4(uint32_t* r, uint32_t addr) {
    asm volatile("ldmatrix.sync.aligned.m8n8.x4.shared.b16 {%0,%1,%2,%3}, [%4];"
                 : "=r"(r[0]), "=r"(r[1]), "=r"(r[2]), "=r"(r[3]) : "r"(addr));
}
__device__ __forceinline__ void mma_bf16(float* c, const uint32_t* a,
                                         uint32_t b0, uint32_t b1) {
    asm volatile(
        "mma.sync.aligned.m16n8k16.row.col.f32.bf16.bf16.f32 "
        "{%0,%1,%2,%3}, {%4,%5,%6,%7}, {%8,%9}, {%0,%1,%2,%3};"
        : "+f"(c[0]), "+f"(c[1]), "+f"(c[2]), "+f"(c[3])
        : "r"(a[0]), "r"(a[1]), "r"(a[2]), "r"(a[3]), "r"(b0), "r"(b1));
}

// ---------------------------------------------------------------------------
// Kernel 1: split Vw into bf16 hi/lo
// ---------------------------------------------------------------------------
__global__ void vwsplit_kernel(const float* __restrict__ Vw) {
    int idx = blockIdx.x * blockDim.x + threadIdx.x;
    if (idx < VV * HH) {
        float v = Vw[idx];
        __nv_bfloat16 hi = __float2bfloat16(v);
        g_vw_hi[idx] = hi;
        g_vw_lo[idx] = __float2bfloat16(v - __bfloat162float(hi));
    }
}

// ---------------------------------------------------------------------------
// Kernel 2: fused ux + recurrence. 32 CTAs (one per batch), 256 threads.
// Thread (j, s): j = hidden row, s = K-half. x[b] preloaded to SMEM once.
// ---------------------------------------------------------------------------
__global__ __launch_bounds__(256, 1) void recurrence_kernel(
    const float* __restrict__ x,  const float* __restrict__ Ww,
    const float* __restrict__ Wb, const float* __restrict__ Uw,
    const float* __restrict__ Ub, float* __restrict__ hidden_out) {
    int b = blockIdx.x;
    int tid = threadIdx.x;
    int j = tid & 127;
    int s = tid >> 7;

    __shared__ alignas(16) float xall[TT * EE];
    __shared__ alignas(16) float hbuf[2][HH];
    __shared__ alignas(16) float psum[2][HH];

    float w[64];
    const float4* wr = (const float4*)(Ww + j * HH + s * 64);
#pragma unroll
    for (int k = 0; k < 16; k++) {
        float4 v = wr[k];
        w[4*k] = v.x; w[4*k+1] = v.y; w[4*k+2] = v.z; w[4*k+3] = v.w;
    }
    float u[16];
    const float4* ur = (const float4*)(Uw + j * EE + s * 16);
#pragma unroll
    for (int k = 0; k < 4; k++) {
        float4 v = ur[k];
        u[4*k] = v.x; u[4*k+1] = v.y; u[4*k+2] = v.z; u[4*k+3] = v.w;
    }
    float bj = (s == 0) ? (Ub[j] + Wb[j]) : 0.f;

    {
        const float4* xsrc = (const float4*)(x + (size_t)b * TT * EE);
        float4* xdst = (float4*)xall;
        for (int i = tid; i < TT * EE / 4; i += 256) xdst[i] = xsrc[i];
    }
    if (s == 0) hbuf[0][j] = 0.f;
    __syncthreads();

    __nv_bfloat16* hs_hi = g_hs_hi + (size_t)b * TT * HH;
    __nv_bfloat16* hs_lo = g_hs_lo + (size_t)b * TT * HH;

    int cur = 0;
    float hv = 0.f;
    for (int t = 0; t < TT; t++) {
        float acc = 0.f;
        const float* xt = xall + t * EE + s * 16;
#pragma unroll
        for (int e = 0; e < 16; e++) acc += u[e] * xt[e];
        const float4* hb = (const float4*)(hbuf[cur] + s * 64);
#pragma unroll
        for (int k = 0; k < 16; k++) {
            float4 h4 = hb[k];
            acc += w[4*k] * h4.x + w[4*k+1] * h4.y + w[4*k+2] * h4.z + w[4*k+3] * h4.w;
        }
        psum[s][j] = acc;
        __syncthreads();
        if (s == 0) {
            hv = tanhf(psum[0][j] + psum[1][j] + bj);
            hbuf[cur ^ 1][j] = hv;
            __nv_bfloat16 hi = __float2bfloat16(hv);
            hs_hi[t * HH + j] = hi;
            hs_lo[t * HH + j] = __float2bfloat16(hv - __bfloat162float(hi));
        }
        __syncthreads();
        cur ^= 1;
    }
    if (s == 0) hidden_out[b * HH + j] = hv;
}

// ---------------------------------------------------------------------------
// Kernel 3: HMMA split-bf16 GEMM. C[6400x8000] = hs @ Vw^T + Vb.
// D = Ah*Bh + Ah*Bl + Al*Bh (fp32 accum). BM=128, BN=160, K=128 resident.
// 256 threads = 8 warps (4m x 2n); warp tile 32x80.
// SMEM rows padded to 272B (17 x 16B chunks) -> ldmatrix conflict-free.
// ---------------------------------------------------------------------------
#define ASTR 272
#define SA_LO_OFF (128 * ASTR)                 // 34816
#define SB_OFF    (2 * 128 * ASTR)             // 69632
#define SB_LO_OFF (160 * ASTR)                 // 43520 (relative to SB_OFF)
#define SBIAS_OFF (SB_OFF + 2 * 160 * ASTR)    // 156672
#define GEMM_SMEM (SBIAS_OFF + 160 * 4)        // 157312

__global__ __launch_bounds__(256, 1) void gemm_hmma_kernel(
    const float* __restrict__ bias, float* __restrict__ C) {
    extern __shared__ char smem[];
    uint32_t sb = smem_u32(smem);
    int tid = threadIdx.x;
    int wid = tid >> 5;
    int lid = tid & 31;
    int warp_m = wid & 3;        // 0..3  -> m offset 32*warp_m
    int warp_n = wid >> 2;       // 0..1  -> n offset 80*warp_n
    int mtile = blockIdx.y * 128;
    int ntile = blockIdx.x * 160;

    // bias tile
    float* bias_s = (float*)(smem + SBIAS_OFF);
    if (tid < 160) bias_s[tid] = bias[ntile + tid];

    // async-load A (128 rows x 16 chunks) hi+lo and B (160 x 16) hi+lo
    {
        const uint4* aH = (const uint4*)g_hs_hi + (size_t)mtile * 16;
        const uint4* aL = (const uint4*)g_hs_lo + (size_t)mtile * 16;
        for (int i = tid; i < 128 * 16; i += 256) {
            int row = i >> 4, c = i & 15;
            uint32_t dst = sb + row * ASTR + c * 16;
            cpasync16(dst, aH + row * 16 + c);
            cpasync16(dst + SA_LO_OFF, aL + row * 16 + c);
        }
        const uint4* bH = (const uint4*)g_vw_hi + (size_t)ntile * 16;
        const uint4* bL = (const uint4*)g_vw_lo + (size_t)ntile * 16;
        for (int i = tid; i < 160 * 16; i += 256) {
            int row = i >> 4, c = i & 15;
            uint32_t dst = sb + SB_OFF + row * ASTR + c * 16;
            cpasync16(dst, bH + row * 16 + c);
            cpasync16(dst + SB_LO_OFF, bL + row * 16 + c);
        }
    }
    cpasync_commit_wait();
    __syncthreads();

    // ldmatrix lane address bases
    // A x4 covers m16 x k16: lanes 0-15 -> m rows, lane/16 -> k chunk (8 elem)
    uint32_t a_addr = sb + (uint32_t)(warp_m * 32 + (lid & 15)) * ASTR
                    + (uint32_t)(lid >> 4) * 16;
    // B x4 covers n16 x k16: n_local = lane%8 + (lane/16)*8, kc = (lane/8)%2
    uint32_t b_addr = sb + SB_OFF
                    + (uint32_t)(warp_n * 80 + (lid & 7) + ((lid >> 4) << 3)) * ASTR
                    + (uint32_t)((lid >> 3) & 1) * 16;

    float acc[2][10][4];
#pragma unroll
    for (int im = 0; im < 2; im++)
#pragma unroll
        for (int s = 0; s < 10; s++)
#pragma unroll
            for (int q = 0; q < 4; q++) acc[im][s][q] = 0.f;

#pragma unroll
    for (int k = 0; k < 8; k++) {
        uint32_t ak = a_addr + k * 32;
        uint32_t bk = b_addr + k * 32;
        uint32_t aH[8], aL[8], bH[20], bL[20];
        ldsm4(aH,     ak);
        ldsm4(aH + 4, ak + 16 * ASTR);
        ldsm4(aL,     ak + SA_LO_OFF);
        ldsm4(aL + 4, ak + SA_LO_OFF + 16 * ASTR);
#pragma unroll
        for (int j = 0; j < 5; j++) {
            ldsm4(bH + j * 4, bk + j * 16 * ASTR);
            ldsm4(bL + j * 4, bk + SB_LO_OFF + j * 16 * ASTR);
        }
#pragma unroll
        for (int im = 0; im < 2; im++) {
#pragma unroll
            for (int s = 0; s < 10; s++) {
                int bi = (s >> 1) * 4 + (s & 1) * 2;
                mma_bf16(acc[im][s], aH + im * 4, bH[bi], bH[bi + 1]);  // Ah*Bh
                mma_bf16(acc[im][s], aH + im * 4, bL[bi], bL[bi + 1]);  // Ah*Bl
                mma_bf16(acc[im][s], aL + im * 4, bH[bi], bH[bi + 1]);  // Al*Bh
            }
        }
    }

    // epilogue: accum layout m16n8: c0,c1 -> row lane/4, cols 2*(lane%4)+{0,1};
    // c2,c3 -> row lane/4+8.
    int r0 = mtile + warp_m * 32 + (lid >> 2);
    int cbase = warp_n * 80 + (lid & 3) * 2;
#pragma unroll
    for (int im = 0; im < 2; im++) {
#pragma unroll
        for (int s = 0; s < 10; s++) {
            int col = cbase + s * 8;
            float b0 = bias_s[col], b1 = bias_s[col + 1];
            float* p0 = C + (size_t)(r0 + im * 16) * VV + ntile + col;
            float* p1 = p0 + (size_t)8 * VV;
            float2 v0 = make_float2(acc[im][s][0] + b0, acc[im][s][1] + b1);
            float2 v1 = make_float2(acc[im][s][2] + b0, acc[im][s][3] + b1);
            *(float2*)p0 = v0;
            *(float2*)p1 = v1;
        }
    }
}

// ---------------------------------------------------------------------------
extern "C" void kernel_launch(void* const* d_in, const int* in_sizes, int n_in,
                              void* d_out, int out_size) {
    const float* x  = (const float*)d_in[0];
    const float* Ww = (const float*)d_in[1];
    const float* Wb = (const float*)d_in[2];
    const float* Uw = (const float*)d_in[3];
    const float* Ub = (const float*)d_in[4];
    const float* Vw = (const float*)d_in[5];
    const float* Vb = (const float*)d_in[6];

    float* out    = (float*)d_out;
    float* hidden = out + (size_t)BB * TT * VV;

    cudaFuncSetAttribute(gemm_hmma_kernel,
                         cudaFuncAttributeMaxDynamicSharedMemorySize, GEMM_SMEM);

    vwsplit_kernel<<<(VV * HH + 511) / 512, 512>>>(Vw);
    recurrence_kernel<<<BB, 256>>>(x, Ww, Wb, Uw, Ub, hidden);
    dim3 grid(VV / 160, MM / 128);
    gemm_hmma_kernel<<<grid, 256, GEMM_SMEM>>>(Vb, out);
}

// round 4
// speedup vs baseline: 2.5925x; 1.1611x over previous
#include <cuda_runtime.h>
#include <cuda_bf16.h>
#include <cstdint>

// Problem constants
#define BB 32
#define TT 200
#define EE 32
#define HH 128
#define VV 8000
#define MM (BB*TT)   // 6400

// Static scratch: bf16 hi/lo splits
__device__ alignas(256) __nv_bfloat16 g_hs_hi[MM * HH];
__device__ alignas(256) __nv_bfloat16 g_hs_lo[MM * HH];
__device__ alignas(256) __nv_bfloat16 g_vw_hi[VV * HH];
__device__ alignas(256) __nv_bfloat16 g_vw_lo[VV * HH];

// ---------------------------------------------------------------------------
// portable PTX helpers (no tcgen05 — compute_103 virtual target)
// ---------------------------------------------------------------------------
__device__ __forceinline__ uint32_t smem_u32(const void* p) {
    uint32_t a;
    asm("{ .reg .u64 t; cvta.to.shared.u64 t, %1; cvt.u32.u64 %0, t; }"
        : "=r"(a) : "l"(p));
    return a;
}
__device__ __forceinline__ void cpasync16(uint32_t dst, const void* src) {
    asm volatile("cp.async.cg.shared.global [%0], [%1], 16;" :: "r"(dst), "l"(src));
}
__device__ __forceinline__ void cpasync_commit() {
    asm volatile("cp.async.commit_group;" ::: "memory");
}
template<int N>
__device__ __forceinline__ void cpasync_wait() {
    asm volatile("cp.async.wait_group %0;" :: "n"(N) : "memory");
}
__device__ __forceinline__ void ldsm4(uint32_t* r, uint32_t addr) {
    asm volatile("ldmatrix.sync.aligned.m8n8.x4.shared.b16 {%0,%1,%2,%3}, [%4];"
                 : "=r"(r[0]), "=r"(r[1]), "=r"(r[2]), "=r"(r[3]) : "r"(addr));
}
__device__ __forceinline__ void mma_bf16(float* c, const uint32_t* a,
                                         uint32_t b0, uint32_t b1) {
    asm volatile(
        "mma.sync.aligned.m16n8k16.row.col.f32.bf16.bf16.f32 "
        "{%0,%1,%2,%3}, {%4,%5,%6,%7}, {%8,%9}, {%0,%1,%2,%3};"
        : "+f"(c[0]), "+f"(c[1]), "+f"(c[2]), "+f"(c[3])
        : "r"(a[0]), "r"(a[1]), "r"(a[2]), "r"(a[3]), "r"(b0), "r"(b1));
}

// ---------------------------------------------------------------------------
// Kernel 1: merged prep.
// CTAs 0..31: fused ux + recurrence (one batch each, 256 thr, K split s=0/1).
// CTAs 32..531: split Vw into bf16 hi/lo (500 CTAs x 2048 elems = VV*HH).
// ---------------------------------------------------------------------------
__global__ __launch_bounds__(256, 1) void prep_kernel(
    const float* __restrict__ x,  const float* __restrict__ Ww,
    const float* __restrict__ Wb, const float* __restrict__ Uw,
    const float* __restrict__ Ub, const float* __restrict__ Vw,
    float* __restrict__ hidden_out) {

    __shared__ alignas(16) float xall[TT * EE];
    __shared__ alignas(16) float hbuf[2][HH];
    __shared__ alignas(16) float psum[2][HH];

    if (blockIdx.x >= 32) {
        // ---- vwsplit part ----
        int base = (blockIdx.x - 32) * 2048 + threadIdx.x;
#pragma unroll
        for (int q = 0; q < 8; q++) {
            int idx = base + q * 256;
            float v = Vw[idx];
            __nv_bfloat16 hi = __float2bfloat16(v);
            g_vw_hi[idx] = hi;
            g_vw_lo[idx] = __float2bfloat16(v - __bfloat162float(hi));
        }
        return;
    }

    // ---- recurrence part ----
    int b = blockIdx.x;
    int tid = threadIdx.x;
    int j = tid & 127;
    int s = tid >> 7;

    float w[64];
    const float4* wr = (const float4*)(Ww + j * HH + s * 64);
#pragma unroll
    for (int k = 0; k < 16; k++) {
        float4 v = wr[k];
        w[4*k] = v.x; w[4*k+1] = v.y; w[4*k+2] = v.z; w[4*k+3] = v.w;
    }
    float u[16];
    const float4* ur = (const float4*)(Uw + j * EE + s * 16);
#pragma unroll
    for (int k = 0; k < 4; k++) {
        float4 v = ur[k];
        u[4*k] = v.x; u[4*k+1] = v.y; u[4*k+2] = v.z; u[4*k+3] = v.w;
    }
    float bj = (s == 0) ? (Ub[j] + Wb[j]) : 0.f;

    {
        const float4* xsrc = (const float4*)(x + (size_t)b * TT * EE);
        float4* xdst = (float4*)xall;
        for (int i = tid; i < TT * EE / 4; i += 256) xdst[i] = xsrc[i];
    }
    if (s == 0) hbuf[0][j] = 0.f;
    __syncthreads();

    __nv_bfloat16* hs_hi = g_hs_hi + (size_t)b * TT * HH;
    __nv_bfloat16* hs_lo = g_hs_lo + (size_t)b * TT * HH;

    int cur = 0;
    float hv = 0.f;
    for (int t = 0; t < TT; t++) {
        float acc = 0.f;
        const float* xt = xall + t * EE + s * 16;
#pragma unroll
        for (int e = 0; e < 16; e++) acc += u[e] * xt[e];
        const float4* hb = (const float4*)(hbuf[cur] + s * 64);
#pragma unroll
        for (int k = 0; k < 16; k++) {
            float4 h4 = hb[k];
            acc += w[4*k] * h4.x + w[4*k+1] * h4.y + w[4*k+2] * h4.z + w[4*k+3] * h4.w;
        }
        psum[s][j] = acc;
        __syncthreads();
        if (s == 0) {
            hv = tanhf(psum[0][j] + psum[1][j] + bj);
            hbuf[cur ^ 1][j] = hv;
            __nv_bfloat16 hi = __float2bfloat16(hv);
            hs_hi[t * HH + j] = hi;
            hs_lo[t * HH + j] = __float2bfloat16(hv - __bfloat162float(hi));
        }
        __syncthreads();
        cur ^= 1;
    }
    if (s == 0) hidden_out[b * HH + j] = hv;
}

// ---------------------------------------------------------------------------
// Kernel 2: HMMA split-bf16 GEMM, 2 m-tiles per CTA, A double-buffered.
// C[6400x8000] = hs @ Vw^T + Vb.   D = Ah*Bh + Ah*Bl + Al*Bh  (fp32 accum)
// Tile 128x160, K=128 resident. 256 thr = 8 warps (4m x 2n), warp tile 32x80.
// SMEM rows: 256B, 16 chunks of 16B, swizzle chunk c -> c ^ (row & 7).
// ---------------------------------------------------------------------------
#define SA0_HI 0
#define SA0_LO 32768
#define SA1_HI 65536
#define SA1_LO 98304
#define SB_HI  131072
#define SB_LO  172032
#define SBIAS  212992
#define GEMM_SMEM (212992 + 640)

__device__ __forceinline__ void load_A(char* smem, uint32_t sb_hi, uint32_t sb_lo,
                                       int mtile, int tid) {
    const uint4* aH = (const uint4*)g_hs_hi + (size_t)mtile * 16;
    const uint4* aL = (const uint4*)g_hs_lo + (size_t)mtile * 16;
#pragma unroll
    for (int i = tid; i < 2048; i += 256) {
        int row = i >> 4, c = i & 15;
        uint32_t off = (uint32_t)row * 256u + (uint32_t)((c ^ (row & 7)) << 4);
        cpasync16(sb_hi + off, aH + i);
        cpasync16(sb_lo + off, aL + i);
    }
}

__device__ __forceinline__ void compute_store(
    char* smem, uint32_t sb, uint32_t abase_hi, uint32_t abase_lo,
    const float* bias_s, float* __restrict__ C,
    int mtile, int ntile, int warp_m, int warp_n, int lid) {

    // lane geometry
    int ra = warp_m * 32 + (lid & 15);          // A row for ldsm (and +16)
    int r7 = ra & 7;
    uint32_t aH_row = abase_hi + (uint32_t)ra * 256u;
    uint32_t aL_row = abase_lo + (uint32_t)ra * 256u;
    int ca = (lid >> 4);                         // 0/1 chunk parity for A

    int nb = warp_n * 80 + (lid & 7) + ((lid >> 4) << 3);   // B row
    int n7 = nb & 7;
    uint32_t bH_row = sb + SB_HI + (uint32_t)nb * 256u;
    uint32_t bL_row = sb + SB_LO + (uint32_t)nb * 256u;
    int cb = ((lid >> 3) & 1);

    float acc[2][10][4];
#pragma unroll
    for (int im = 0; im < 2; im++)
#pragma unroll
        for (int s = 0; s < 10; s++)
#pragma unroll
            for (int q = 0; q < 4; q++) acc[im][s][q] = 0.f;

#pragma unroll
    for (int k = 0; k < 8; k++) {
        uint32_t offA = (uint32_t)(((k * 2 + ca) ^ r7) << 4);
        uint32_t offB = (uint32_t)(((k * 2 + cb) ^ n7) << 4);
        uint32_t aH[8], aL[8], bH[20], bL[20];
        ldsm4(aH,     aH_row + offA);
        ldsm4(aH + 4, aH_row + 4096 + offA);    // +16 rows
        ldsm4(aL,     aL_row + offA);
        ldsm4(aL + 4, aL_row + 4096 + offA);
#pragma unroll
        for (int jj = 0; jj < 5; jj++) {
            ldsm4(bH + jj * 4, bH_row + jj * 4096 + offB);
            ldsm4(bL + jj * 4, bL_row + jj * 4096 + offB);
        }
#pragma unroll
        for (int im = 0; im < 2; im++) {
#pragma unroll
            for (int s = 0; s < 10; s++) {
                int bi = (s >> 1) * 4 + (s & 1) * 2;
                mma_bf16(acc[im][s], aH + im * 4, bH[bi], bH[bi + 1]);
                mma_bf16(acc[im][s], aH + im * 4, bL[bi], bL[bi + 1]);
                mma_bf16(acc[im][s], aL + im * 4, bH[bi], bH[bi + 1]);
            }
        }
    }

    int r0 = mtile + warp_m * 32 + (lid >> 2);
    int cbase = warp_n * 80 + (lid & 3) * 2;
#pragma unroll
    for (int im = 0; im < 2; im++) {
#pragma unroll
        for (int s = 0; s < 10; s++) {
            int col = cbase + s * 8;
            float b0 = bias_s[col], b1 = bias_s[col + 1];
            float* p0 = C + (size_t)(r0 + im * 16) * VV + ntile + col;
            float* p1 = p0 + (size_t)8 * VV;
            *(float2*)p0 = make_float2(acc[im][s][0] + b0, acc[im][s][1] + b1);
            *(float2*)p1 = make_float2(acc[im][s][2] + b0, acc[im][s][3] + b1);
        }
    }
}

__global__ __launch_bounds__(256, 1) void gemm_hmma_kernel(
    const float* __restrict__ bias, float* __restrict__ C) {
    extern __shared__ char smem[];
    uint32_t sb = smem_u32(smem);
    int tid = threadIdx.x;
    int wid = tid >> 5;
    int lid = tid & 31;
    int warp_m = wid & 3;
    int warp_n = wid >> 2;
    int ntile = blockIdx.x * 160;
    int mtile0 = blockIdx.y * 256;     // this CTA does mtile0 and mtile0+128

    // bias tile (plain loads; published by first __syncthreads)
    float* bias_s = (float*)(smem + SBIAS);
    if (tid < 160) bias_s[tid] = bias[ntile + tid];

    // B tile (hi+lo) + A tile 0  -> group 0
    {
        const uint4* bH = (const uint4*)g_vw_hi + (size_t)ntile * 16;
        const uint4* bL = (const uint4*)g_vw_lo + (size_t)ntile * 16;
#pragma unroll
        for (int i = tid; i < 2560; i += 256) {
            int row = i >> 4, c = i & 15;
            uint32_t off = (uint32_t)row * 256u + (uint32_t)((c ^ (row & 7)) << 4);
            cpasync16(sb + SB_HI + off, bH + i);
            cpasync16(sb + SB_LO + off, bL + i);
        }
    }
    load_A(smem, sb + SA0_HI, sb + SA0_LO, mtile0, tid);
    cpasync_commit();
    // A tile 1 -> group 1 (streams under tile-0 math)
    load_A(smem, sb + SA1_HI, sb + SA1_LO, mtile0 + 128, tid);
    cpasync_commit();

    cpasync_wait<1>();     // group 0 (B + A0) complete
    __syncthreads();
    compute_store(smem, sb, sb + SA0_HI, sb + SA0_LO, bias_s, C,
                  mtile0, ntile, warp_m, warp_n, lid);

    cpasync_wait<0>();     // A1 complete
    __syncthreads();
    compute_store(smem, sb, sb + SA1_HI, sb + SA1_LO, bias_s, C,
                  mtile0 + 128, ntile, warp_m, warp_n, lid);
}

// ---------------------------------------------------------------------------
extern "C" void kernel_launch(void* const* d_in, const int* in_sizes, int n_in,
                              void* d_out, int out_size) {
    const float* x  = (const float*)d_in[0];
    const float* Ww = (const float*)d_in[1];
    const float* Wb = (const float*)d_in[2];
    const float* Uw = (const float*)d_in[3];
    const float* Ub = (const float*)d_in[4];
    const float* Vw = (const float*)d_in[5];
    const float* Vb = (const float*)d_in[6];

    float* out    = (float*)d_out;
    float* hidden = out + (size_t)BB * TT * VV;

    cudaFuncSetAttribute(gemm_hmma_kernel,
                         cudaFuncAttributeMaxDynamicSharedMemorySize, GEMM_SMEM);

    prep_kernel<<<532, 256>>>(x, Ww, Wb, Uw, Ub, Vw, hidden);
    dim3 grid(VV / 160, MM / 256);
    gemm_hmma_kernel<<<grid, 256, GEMM_SMEM>>>(Vb, out);
}

// round 5
// speedup vs baseline: 2.6729x; 1.0310x over previous
#include <cuda_runtime.h>
#include <cuda_bf16.h>
#include <cstdint>

// Problem constants
#define BB 32
#define TT 200
#define EE 32
#define HH 128
#define VV 8000
#define MM (BB*TT)   // 6400

// Static scratch: bf16 hi/lo splits
__device__ alignas(256) __nv_bfloat16 g_hs_hi[MM * HH];
__device__ alignas(256) __nv_bfloat16 g_hs_lo[MM * HH];
__device__ alignas(256) __nv_bfloat16 g_vw_hi[VV * HH];
__device__ alignas(256) __nv_bfloat16 g_vw_lo[VV * HH];

// ---------------------------------------------------------------------------
// portable PTX helpers (no tcgen05 — compute_103 virtual target)
// ---------------------------------------------------------------------------
__device__ __forceinline__ uint32_t smem_u32(const void* p) {
    uint32_t a;
    asm("{ .reg .u64 t; cvta.to.shared.u64 t, %1; cvt.u32.u64 %0, t; }"
        : "=r"(a) : "l"(p));
    return a;
}
__device__ __forceinline__ void cpasync16(uint32_t dst, const void* src) {
    asm volatile("cp.async.cg.shared.global [%0], [%1], 16;" :: "r"(dst), "l"(src));
}
__device__ __forceinline__ void cpasync_commit() {
    asm volatile("cp.async.commit_group;" ::: "memory");
}
template<int N>
__device__ __forceinline__ void cpasync_wait() {
    asm volatile("cp.async.wait_group %0;" :: "n"(N) : "memory");
}
__device__ __forceinline__ void ldsm4(uint32_t* r, uint32_t addr) {
    asm volatile("ldmatrix.sync.aligned.m8n8.x4.shared.b16 {%0,%1,%2,%3}, [%4];"
                 : "=r"(r[0]), "=r"(r[1]), "=r"(r[2]), "=r"(r[3]) : "r"(addr));
}
__device__ __forceinline__ void mma_bf16(float* c, const uint32_t* a,
                                         uint32_t b0, uint32_t b1) {
    asm volatile(
        "mma.sync.aligned.m16n8k16.row.col.f32.bf16.bf16.f32 "
        "{%0,%1,%2,%3}, {%4,%5,%6,%7}, {%8,%9}, {%0,%1,%2,%3};"
        : "+f"(c[0]), "+f"(c[1]), "+f"(c[2]), "+f"(c[3])
        : "r"(a[0]), "r"(a[1]), "r"(a[2]), "r"(a[3]), "r"(b0), "r"(b1));
}
// fast tanh: rel err ~1e-6 (MUFU.EX2 + approx div), handles |x| large exactly
__device__ __forceinline__ float ftanh(float x) {
    float e = __expf(2.f * x);
    return 1.f - __fdividef(2.f, e + 1.f);
}

// ---------------------------------------------------------------------------
// Kernel 1: merged prep.
// CTAs 0..31: fused ux + recurrence (one batch each, 256 thr).
//   lane layout: j = warp*16 + (lane&15), s = lane>>4 (K half).
//   reduction via shfl.bfly(16); ONE __syncthreads per step.
// CTAs 32..531: split Vw into bf16 hi/lo.
// ---------------------------------------------------------------------------
__global__ __launch_bounds__(256, 1) void prep_kernel(
    const float* __restrict__ x,  const float* __restrict__ Ww,
    const float* __restrict__ Wb, const float* __restrict__ Uw,
    const float* __restrict__ Ub, const float* __restrict__ Vw,
    float* __restrict__ hidden_out) {

    __shared__ alignas(16) float xall[TT * EE];
    __shared__ alignas(16) float hbuf[2][HH];

    if (blockIdx.x >= 32) {
        int base = (blockIdx.x - 32) * 2048 + threadIdx.x;
#pragma unroll
        for (int q = 0; q < 8; q++) {
            int idx = base + q * 256;
            float v = Vw[idx];
            __nv_bfloat16 hi = __float2bfloat16(v);
            g_vw_hi[idx] = hi;
            g_vw_lo[idx] = __float2bfloat16(v - __bfloat162float(hi));
        }
        return;
    }

    int b = blockIdx.x;
    int tid = threadIdx.x;
    int wrp = tid >> 5;
    int lane = tid & 31;
    int j = wrp * 16 + (lane & 15);
    int s = lane >> 4;

    float w[64];
    const float4* wr = (const float4*)(Ww + j * HH + s * 64);
#pragma unroll
    for (int k = 0; k < 16; k++) {
        float4 v = wr[k];
        w[4*k] = v.x; w[4*k+1] = v.y; w[4*k+2] = v.z; w[4*k+3] = v.w;
    }
    float u[16];
    const float4* ur = (const float4*)(Uw + j * EE + s * 16);
#pragma unroll
    for (int k = 0; k < 4; k++) {
        float4 v = ur[k];
        u[4*k] = v.x; u[4*k+1] = v.y; u[4*k+2] = v.z; u[4*k+3] = v.w;
    }
    float bj = Ub[j] + Wb[j];    // every lane holds it (added after reduction)

    {
        const float4* xsrc = (const float4*)(x + (size_t)b * TT * EE);
        float4* xdst = (float4*)xall;
        for (int i = tid; i < TT * EE / 4; i += 256) xdst[i] = xsrc[i];
    }
    if (tid < HH) hbuf[0][tid] = 0.f;
    __syncthreads();

    __nv_bfloat16* hs_hi = g_hs_hi + (size_t)b * TT * HH;
    __nv_bfloat16* hs_lo = g_hs_lo + (size_t)b * TT * HH;

    int cur = 0;
    float hv = 0.f;
    for (int t = 0; t < TT; t++) {
        float a0 = 0.f, a1 = 0.f, a2 = 0.f, a3 = 0.f;
        const float4* xt = (const float4*)(xall + t * EE + s * 16);
#pragma unroll
        for (int e = 0; e < 4; e++) {
            float4 x4 = xt[e];
            a0 += u[4*e] * x4.x;   a1 += u[4*e+1] * x4.y;
            a2 += u[4*e+2] * x4.z; a3 += u[4*e+3] * x4.w;
        }
        const float4* hb = (const float4*)(hbuf[cur] + s * 64);
#pragma unroll
        for (int k = 0; k < 16; k++) {
            float4 h4 = hb[k];
            a0 += w[4*k] * h4.x;   a1 += w[4*k+1] * h4.y;
            a2 += w[4*k+2] * h4.z; a3 += w[4*k+3] * h4.w;
        }
        float acc = (a0 + a1) + (a2 + a3);
        acc += __shfl_xor_sync(0xffffffffu, acc, 16);
        hv = ftanh(acc + bj);
        __nv_bfloat16 hi = __float2bfloat16(hv);
        if (s == 0) {
            hbuf[cur ^ 1][j] = hv;
            hs_hi[t * HH + j] = hi;
        } else {
            hs_lo[t * HH + j] = __float2bfloat16(hv - __bfloat162float(hi));
        }
        __syncthreads();
        cur ^= 1;
    }
    if (s == 0) hidden_out[b * HH + j] = hv;
}

// ---------------------------------------------------------------------------
// Kernel 2: HMMA split-bf16 GEMM, 2 m-tiles per CTA, A tiles double-buffered
// via cp.async groups; fragments double-buffered in registers across k-steps;
// split terms ordered outermost to break accumulator RAW chains.
// C[6400x8000] = hs @ Vw^T + Vb.   D = Ah*Bh + Ah*Bl + Al*Bh  (fp32 accum)
// Tile 128x160, K=128 resident. 256 thr = 8 warps (4m x 2n), warp tile 32x80.
// SMEM rows: 256B, 16 chunks of 16B, swizzle chunk c -> c ^ (row & 7).
// ---------------------------------------------------------------------------
#define SA0_HI 0
#define SA0_LO 32768
#define SA1_HI 65536
#define SA1_LO 98304
#define SB_HI  131072
#define SB_LO  172032
#define SBIAS  212992
#define GEMM_SMEM (212992 + 640)

__device__ __forceinline__ void load_A(uint32_t sb_hi, uint32_t sb_lo,
                                       int mtile, int tid) {
    const uint4* aH = (const uint4*)g_hs_hi + (size_t)mtile * 16;
    const uint4* aL = (const uint4*)g_hs_lo + (size_t)mtile * 16;
#pragma unroll
    for (int i = tid; i < 2048; i += 256) {
        int row = i >> 4, c = i & 15;
        uint32_t off = (uint32_t)row * 256u + (uint32_t)((c ^ (row & 7)) << 4);
        cpasync16(sb_hi + off, aH + i);
        cpasync16(sb_lo + off, aL + i);
    }
}

struct Frags {
    uint32_t aH[8], aL[8], bH[20], bL[20];
};

__device__ __forceinline__ void load_frags(
    Frags& f, int k, uint32_t aH_row, uint32_t aL_row,
    uint32_t bH_row, uint32_t bL_row, int r7, int n7, int ca, int cb) {
    uint32_t offA = (uint32_t)(((k * 2 + ca) ^ r7) << 4);
    uint32_t offB = (uint32_t)(((k * 2 + cb) ^ n7) << 4);
    ldsm4(f.aH,     aH_row + offA);
    ldsm4(f.aH + 4, aH_row + 4096 + offA);
    ldsm4(f.aL,     aL_row + offA);
    ldsm4(f.aL + 4, aL_row + 4096 + offA);
#pragma unroll
    for (int jj = 0; jj < 5; jj++) {
        ldsm4(f.bH + jj * 4, bH_row + jj * 4096 + offB);
        ldsm4(f.bL + jj * 4, bL_row + jj * 4096 + offB);
    }
}

__device__ __forceinline__ void compute_store(
    uint32_t sb, uint32_t abase_hi, uint32_t abase_lo,
    const float* bias_s, float* __restrict__ C,
    int mtile, int ntile, int warp_m, int warp_n, int lid) {

    int ra = warp_m * 32 + (lid & 15);
    int r7 = ra & 7;
    uint32_t aH_row = abase_hi + (uint32_t)ra * 256u;
    uint32_t aL_row = abase_lo + (uint32_t)ra * 256u;
    int ca = (lid >> 4);

    int nb = warp_n * 80 + (lid & 7) + ((lid >> 4) << 3);
    int n7 = nb & 7;
    uint32_t bH_row = sb + SB_HI + (uint32_t)nb * 256u;
    uint32_t bL_row = sb + SB_LO + (uint32_t)nb * 256u;
    int cb = ((lid >> 3) & 1);

    float acc[2][10][4];
#pragma unroll
    for (int im = 0; im < 2; im++)
#pragma unroll
        for (int s = 0; s < 10; s++)
#pragma unroll
            for (int q = 0; q < 4; q++) acc[im][s][q] = 0.f;

    Frags fr[2];
    load_frags(fr[0], 0, aH_row, aL_row, bH_row, bL_row, r7, n7, ca, cb);

#pragma unroll
    for (int k = 0; k < 8; k++) {
        if (k < 7)
            load_frags(fr[(k + 1) & 1], k + 1, aH_row, aL_row, bH_row, bL_row,
                       r7, n7, ca, cb);
        Frags& f = fr[k & 1];
        // term 0: Ah*Bh
#pragma unroll
        for (int im = 0; im < 2; im++)
#pragma unroll
            for (int s = 0; s < 10; s++) {
                int bi = (s >> 1) * 4 + (s & 1) * 2;
                mma_bf16(acc[im][s], f.aH + im * 4, f.bH[bi], f.bH[bi + 1]);
            }
        // term 1: Ah*Bl
#pragma unroll
        for (int im = 0; im < 2; im++)
#pragma unroll
            for (int s = 0; s < 10; s++) {
                int bi = (s >> 1) * 4 + (s & 1) * 2;
                mma_bf16(acc[im][s], f.aH + im * 4, f.bL[bi], f.bL[bi + 1]);
            }
        // term 2: Al*Bh
#pragma unroll
        for (int im = 0; im < 2; im++)
#pragma unroll
            for (int s = 0; s < 10; s++) {
                int bi = (s >> 1) * 4 + (s & 1) * 2;
                mma_bf16(acc[im][s], f.aL + im * 4, f.bH[bi], f.bH[bi + 1]);
            }
    }

    int r0 = mtile + warp_m * 32 + (lid >> 2);
    int cbase = warp_n * 80 + (lid & 3) * 2;
#pragma unroll
    for (int im = 0; im < 2; im++) {
#pragma unroll
        for (int s = 0; s < 10; s++) {
            int col = cbase + s * 8;
            float b0 = bias_s[col], b1 = bias_s[col + 1];
            float* p0 = C + (size_t)(r0 + im * 16) * VV + ntile + col;
            float* p1 = p0 + (size_t)8 * VV;
            *(float2*)p0 = make_float2(acc[im][s][0] + b0, acc[im][s][1] + b1);
            *(float2*)p1 = make_float2(acc[im][s][2] + b0, acc[im][s][3] + b1);
        }
    }
}

__global__ __launch_bounds__(256, 1) void gemm_hmma_kernel(
    const float* __restrict__ bias, float* __restrict__ C) {
    extern __shared__ char smem[];
    uint32_t sb = smem_u32(smem);
    int tid = threadIdx.x;
    int wid = tid >> 5;
    int lid = tid & 31;
    int warp_m = wid & 3;
    int warp_n = wid >> 2;
    int ntile = blockIdx.x * 160;
    int mtile0 = blockIdx.y * 256;

    float* bias_s = (float*)(smem + SBIAS);
    if (tid < 160) bias_s[tid] = bias[ntile + tid];

    {
        const uint4* bH = (const uint4*)g_vw_hi + (size_t)ntile * 16;
        const uint4* bL = (const uint4*)g_vw_lo + (size_t)ntile * 16;
#pragma unroll
        for (int i = tid; i < 2560; i += 256) {
            int row = i >> 4, c = i & 15;
            uint32_t off = (uint32_t)row * 256u + (uint32_t)((c ^ (row & 7)) << 4);
            cpasync16(sb + SB_HI + off, bH + i);
            cpasync16(sb + SB_LO + off, bL + i);
        }
    }
    load_A(sb + SA0_HI, sb + SA0_LO, mtile0, tid);
    cpasync_commit();
    load_A(sb + SA1_HI, sb + SA1_LO, mtile0 + 128, tid);
    cpasync_commit();

    cpasync_wait<1>();
    __syncthreads();
    compute_store(sb, sb + SA0_HI, sb + SA0_LO, bias_s, C,
                  mtile0, ntile, warp_m, warp_n, lid);

    cpasync_wait<0>();
    __syncthreads();
    compute_store(sb, sb + SA1_HI, sb + SA1_LO, bias_s, C,
                  mtile0 + 128, ntile, warp_m, warp_n, lid);
}

// ---------------------------------------------------------------------------
extern "C" void kernel_launch(void* const* d_in, const int* in_sizes, int n_in,
                              void* d_out, int out_size) {
    const float* x  = (const float*)d_in[0];
    const float* Ww = (const float*)d_in[1];
    const float* Wb = (const float*)d_in[2];
    const float* Uw = (const float*)d_in[3];
    const float* Ub = (const float*)d_in[4];
    const float* Vw = (const float*)d_in[5];
    const float* Vb = (const float*)d_in[6];

    float* out    = (float*)d_out;
    float* hidden = out + (size_t)BB * TT * VV;

    cudaFuncSetAttribute(gemm_hmma_kernel,
                         cudaFuncAttributeMaxDynamicSharedMemorySize, GEMM_SMEM);

    prep_kernel<<<532, 256>>>(x, Ww, Wb, Uw, Ub, Vw, hidden);
    dim3 grid(VV / 160, MM / 256);
    gemm_hmma_kernel<<<grid, 256, GEMM_SMEM>>>(Vb, out);
}

// round 6
// speedup vs baseline: 3.0903x; 1.1562x over previous
#include <cuda_runtime.h>
#include <cuda_bf16.h>
#include <cstdint>

// Problem constants
#define BB 32
#define TT 200
#define EE 32
#define HH 128
#define VV 8000
#define MM (BB*TT)   // 6400

// Static scratch: bf16 hi/lo splits
__device__ alignas(256) __nv_bfloat16 g_hs_hi[MM * HH];
__device__ alignas(256) __nv_bfloat16 g_hs_lo[MM * HH];
__device__ alignas(256) __nv_bfloat16 g_vw_hi[VV * HH];
__device__ alignas(256) __nv_bfloat16 g_vw_lo[VV * HH];

// ---------------------------------------------------------------------------
// portable PTX helpers (no tcgen05 — compute_103 virtual target)
// ---------------------------------------------------------------------------
__device__ __forceinline__ uint32_t smem_u32(const void* p) {
    uint32_t a;
    asm("{ .reg .u64 t; cvta.to.shared.u64 t, %1; cvt.u32.u64 %0, t; }"
        : "=r"(a) : "l"(p));
    return a;
}
__device__ __forceinline__ void cpasync16(uint32_t dst, const void* src) {
    asm volatile("cp.async.cg.shared.global [%0], [%1], 16;" :: "r"(dst), "l"(src));
}
__device__ __forceinline__ void cpasync_commit() {
    asm volatile("cp.async.commit_group;" ::: "memory");
}
template<int N>
__device__ __forceinline__ void cpasync_wait() {
    asm volatile("cp.async.wait_group %0;" :: "n"(N) : "memory");
}
__device__ __forceinline__ void ldsm4(uint32_t* r, uint32_t addr) {
    asm volatile("ldmatrix.sync.aligned.m8n8.x4.shared.b16 {%0,%1,%2,%3}, [%4];"
                 : "=r"(r[0]), "=r"(r[1]), "=r"(r[2]), "=r"(r[3]) : "r"(addr));
}
__device__ __forceinline__ void ldsm2(uint32_t* r, uint32_t addr) {
    asm volatile("ldmatrix.sync.aligned.m8n8.x2.shared.b16 {%0,%1}, [%2];"
                 : "=r"(r[0]), "=r"(r[1]) : "r"(addr));
}
__device__ __forceinline__ void mma_bf16(float* c, const uint32_t* a,
                                         uint32_t b0, uint32_t b1) {
    asm volatile(
        "mma.sync.aligned.m16n8k16.row.col.f32.bf16.bf16.f32 "
        "{%0,%1,%2,%3}, {%4,%5,%6,%7}, {%8,%9}, {%0,%1,%2,%3};"
        : "+f"(c[0]), "+f"(c[1]), "+f"(c[2]), "+f"(c[3])
        : "r"(a[0]), "r"(a[1]), "r"(a[2]), "r"(a[3]), "r"(b0), "r"(b1));
}
// packed f32x2 FMA (Blackwell FFMA2; base PTX 8.6, sm_100+ family)
#define FFMA2(acc, a, b) \
    asm("fma.rn.f32x2 %0, %1, %2, %0;" : "+l"(acc) : "l"(a), "l"(b))
#define UNPACK2(lo, hi, v) \
    asm("mov.b64 {%0, %1}, %2;" : "=f"(lo), "=f"(hi) : "l"(v))

// fast tanh: rel err ~1e-6
__device__ __forceinline__ float ftanh(float x) {
    float e = __expf(2.f * x);
    return 1.f - __fdividef(2.f, e + 1.f);
}

// ---------------------------------------------------------------------------
// Kernel 1: merged prep.
// CTAs 0..31: fused ux + recurrence (one batch each, 256 thr).
//   j = warp*16 + (lane&15), s = lane>>4; shfl.bfly(16) reduction; one
//   barrier per step. W@h and U@x done with packed f32x2 FFMA2 (half issue).
// CTAs 32..531: split Vw into bf16 hi/lo.
// ---------------------------------------------------------------------------
__global__ __launch_bounds__(256, 1) void prep_kernel(
    const float* __restrict__ x,  const float* __restrict__ Ww,
    const float* __restrict__ Wb, const float* __restrict__ Uw,
    const float* __restrict__ Ub, const float* __restrict__ Vw,
    float* __restrict__ hidden_out) {

    __shared__ alignas(16) float xall[TT * EE];
    __shared__ alignas(16) float hbuf[2][HH];

    if (blockIdx.x >= 32) {
        int base = (blockIdx.x - 32) * 2048 + threadIdx.x;
#pragma unroll
        for (int q = 0; q < 8; q++) {
            int idx = base + q * 256;
            float v = Vw[idx];
            __nv_bfloat16 hi = __float2bfloat16(v);
            g_vw_hi[idx] = hi;
            g_vw_lo[idx] = __float2bfloat16(v - __bfloat162float(hi));
        }
        return;
    }

    int b = blockIdx.x;
    int tid = threadIdx.x;
    int wrp = tid >> 5;
    int lane = tid & 31;
    int j = wrp * 16 + (lane & 15);
    int s = lane >> 4;

    // packed weights: 64 floats -> 32 f32x2 (u64), via 16B loads
    unsigned long long w2[32];
    {
        const ulonglong2* wr = (const ulonglong2*)(Ww + j * HH + s * 64);
#pragma unroll
        for (int k = 0; k < 16; k++) {
            ulonglong2 v = wr[k];
            w2[2 * k] = v.x; w2[2 * k + 1] = v.y;
        }
    }
    unsigned long long u2[8];
    {
        const ulonglong2* ur = (const ulonglong2*)(Uw + j * EE + s * 16);
#pragma unroll
        for (int k = 0; k < 4; k++) {
            ulonglong2 v = ur[k];
            u2[2 * k] = v.x; u2[2 * k + 1] = v.y;
        }
    }
    float bj = Ub[j] + Wb[j];

    {
        const float4* xsrc = (const float4*)(x + (size_t)b * TT * EE);
        float4* xdst = (float4*)xall;
        for (int i = tid; i < TT * EE / 4; i += 256) xdst[i] = xsrc[i];
    }
    if (tid < HH) hbuf[0][tid] = 0.f;
    __syncthreads();

    __nv_bfloat16* hs_hi = g_hs_hi + (size_t)b * TT * HH;
    __nv_bfloat16* hs_lo = g_hs_lo + (size_t)b * TT * HH;

    int cur = 0;
    float hv = 0.f;
    for (int t = 0; t < TT; t++) {
        unsigned long long acc01 = 0ull, acc23 = 0ull;   // f32x2 {0,0}
        const ulonglong2* xt = (const ulonglong2*)(xall + t * EE + s * 16);
#pragma unroll
        for (int e = 0; e < 4; e++) {
            ulonglong2 x2 = xt[e];
            FFMA2(acc01, u2[2 * e], x2.x);
            FFMA2(acc23, u2[2 * e + 1], x2.y);
        }
        const ulonglong2* hb = (const ulonglong2*)(hbuf[cur] + s * 64);
#pragma unroll
        for (int k = 0; k < 16; k++) {
            ulonglong2 h2 = hb[k];
            FFMA2(acc01, w2[2 * k], h2.x);
            FFMA2(acc23, w2[2 * k + 1], h2.y);
        }
        float p0, p1, p2, p3;
        UNPACK2(p0, p1, acc01);
        UNPACK2(p2, p3, acc23);
        float acc = (p0 + p1) + (p2 + p3);
        acc += __shfl_xor_sync(0xffffffffu, acc, 16);
        hv = ftanh(acc + bj);
        __nv_bfloat16 hi = __float2bfloat16(hv);
        if (s == 0) {
            hbuf[cur ^ 1][j] = hv;
            hs_hi[t * HH + j] = hi;
        } else {
            hs_lo[t * HH + j] = __float2bfloat16(hv - __bfloat162float(hi));
        }
        __syncthreads();
        cur ^= 1;
    }
    if (s == 0) hidden_out[b * HH + j] = hv;
}

// ---------------------------------------------------------------------------
// Kernel 2: HMMA split-bf16 GEMM, tile 128x80, 2 CTAs/SM (smem ~105KB).
// C[6400x8000] = hs @ Vw^T + Vb.   D = Ah*Bh + Ah*Bl + Al*Bh  (fp32 accum)
// K=128 resident. 256 thr = 8 warps (4m x 2n), warp tile 32x40.
// SMEM rows: 256B, 16 chunks of 16B, swizzle chunk c -> c ^ (row & 7).
// ---------------------------------------------------------------------------
#define SA_HI 0
#define SA_LO 32768
#define SB_HI 65536
#define SB_LO 86016
#define SBIAS 106496
#define GEMM_SMEM (106496 + 320)

__global__ __launch_bounds__(256, 2) void gemm_hmma_kernel(
    const float* __restrict__ bias, float* __restrict__ C) {
    extern __shared__ char smem[];
    uint32_t sb = smem_u32(smem);
    int tid = threadIdx.x;
    int wid = tid >> 5;
    int lid = tid & 31;
    int warp_m = wid & 3;        // m offset 32*warp_m
    int warp_n = wid >> 2;       // n offset 40*warp_n
    int ntile = blockIdx.x * 80;
    int mtile = blockIdx.y * 128;

    float* bias_s = (float*)(smem + SBIAS);
    if (tid < 80) bias_s[tid] = bias[ntile + tid];

    // B tiles (80 rows x 16 chunks, hi+lo)
    {
        const uint4* bH = (const uint4*)g_vw_hi + (size_t)ntile * 16;
        const uint4* bL = (const uint4*)g_vw_lo + (size_t)ntile * 16;
#pragma unroll
        for (int i = tid; i < 1280; i += 256) {
            int row = i >> 4, c = i & 15;
            uint32_t off = (uint32_t)row * 256u + (uint32_t)((c ^ (row & 7)) << 4);
            cpasync16(sb + SB_HI + off, bH + i);
            cpasync16(sb + SB_LO + off, bL + i);
        }
    }
    // A tiles (128 rows x 16 chunks, hi+lo)
    {
        const uint4* aH = (const uint4*)g_hs_hi + (size_t)mtile * 16;
        const uint4* aL = (const uint4*)g_hs_lo + (size_t)mtile * 16;
#pragma unroll
        for (int i = tid; i < 2048; i += 256) {
            int row = i >> 4, c = i & 15;
            uint32_t off = (uint32_t)row * 256u + (uint32_t)((c ^ (row & 7)) << 4);
            cpasync16(sb + SA_HI + off, aH + i);
            cpasync16(sb + SA_LO + off, aL + i);
        }
    }
    cpasync_commit();
    cpasync_wait<0>();
    __syncthreads();

    // lane geometry
    int ra = warp_m * 32 + (lid & 15);
    int r7 = ra & 7;
    uint32_t aH_row = sb + SA_HI + (uint32_t)ra * 256u;
    uint32_t aL_row = sb + SA_LO + (uint32_t)ra * 256u;
    int ca = (lid >> 4);

    int nb4 = warp_n * 40 + (lid & 7) + ((lid >> 4) << 3);   // rows 0..31 of warp's B
    int nb2 = warp_n * 40 + 32 + (lid & 7);                  // rows 32..39 (x2 tail)
    int n7 = lid & 7;                                        // low3 identical for both
    int cb = (lid >> 3) & 1;
    uint32_t bH4 = sb + SB_HI + (uint32_t)nb4 * 256u;
    uint32_t bL4 = sb + SB_LO + (uint32_t)nb4 * 256u;
    uint32_t bH2 = sb + SB_HI + (uint32_t)nb2 * 256u;
    uint32_t bL2 = sb + SB_LO + (uint32_t)nb2 * 256u;

    float acc[2][5][4];
#pragma unroll
    for (int im = 0; im < 2; im++)
#pragma unroll
        for (int s = 0; s < 5; s++)
#pragma unroll
            for (int q = 0; q < 4; q++) acc[im][s][q] = 0.f;

#pragma unroll
    for (int k = 0; k < 8; k++) {
        uint32_t offA = (uint32_t)(((k * 2 + ca) ^ r7) << 4);
        uint32_t offB = (uint32_t)(((k * 2 + cb) ^ n7) << 4);
        uint32_t aH[8], aL[8], bH[10], bL[10];
        ldsm4(aH,     aH_row + offA);
        ldsm4(aH + 4, aH_row + 4096 + offA);
        ldsm4(aL,     aL_row + offA);
        ldsm4(aL + 4, aL_row + 4096 + offA);
        ldsm4(bH,     bH4 + offB);
        ldsm4(bH + 4, bH4 + 4096 + offB);
        ldsm2(bH + 8, bH2 + offB);
        ldsm4(bL,     bL4 + offB);
        ldsm4(bL + 4, bL4 + 4096 + offB);
        ldsm2(bL + 8, bL2 + offB);
        // term 0: Ah*Bh
#pragma unroll
        for (int im = 0; im < 2; im++)
#pragma unroll
            for (int s = 0; s < 5; s++)
                mma_bf16(acc[im][s], aH + im * 4, bH[s * 2], bH[s * 2 + 1]);
        // term 1: Ah*Bl
#pragma unroll
        for (int im = 0; im < 2; im++)
#pragma unroll
            for (int s = 0; s < 5; s++)
                mma_bf16(acc[im][s], aH + im * 4, bL[s * 2], bL[s * 2 + 1]);
        // term 2: Al*Bh
#pragma unroll
        for (int im = 0; im < 2; im++)
#pragma unroll
            for (int s = 0; s < 5; s++)
                mma_bf16(acc[im][s], aL + im * 4, bH[s * 2], bH[s * 2 + 1]);
    }

    int r0 = mtile + warp_m * 32 + (lid >> 2);
    int cbase = warp_n * 40 + (lid & 3) * 2;
#pragma unroll
    for (int im = 0; im < 2; im++) {
#pragma unroll
        for (int s = 0; s < 5; s++) {
            int col = cbase + s * 8;
            float b0 = bias_s[col], b1 = bias_s[col + 1];
            float* p0 = C + (size_t)(r0 + im * 16) * VV + ntile + col;
            float* p1 = p0 + (size_t)8 * VV;
            *(float2*)p0 = make_float2(acc[im][s][0] + b0, acc[im][s][1] + b1);
            *(float2*)p1 = make_float2(acc[im][s][2] + b0, acc[im][s][3] + b1);
        }
    }
}

// ---------------------------------------------------------------------------
extern "C" void kernel_launch(void* const* d_in, const int* in_sizes, int n_in,
                              void* d_out, int out_size) {
    const float* x  = (const float*)d_in[0];
    const float* Ww = (const float*)d_in[1];
    const float* Wb = (const float*)d_in[2];
    const float* Uw = (const float*)d_in[3];
    const float* Ub = (const float*)d_in[4];
    const float* Vw = (const float*)d_in[5];
    const float* Vb = (const float*)d_in[6];

    float* out    = (float*)d_out;
    float* hidden = out + (size_t)BB * TT * VV;

    cudaFuncSetAttribute(gemm_hmma_kernel,
                         cudaFuncAttributeMaxDynamicSharedMemorySize, GEMM_SMEM);

    prep_kernel<<<532, 256>>>(x, Ww, Wb, Uw, Ub, Vw, hidden);
    dim3 grid(VV / 80, MM / 128);
    gemm_hmma_kernel<<<grid, 256, GEMM_SMEM>>>(Vb, out);
}